// round 2
// baseline (speedup 1.0000x reference)
#include <cuda_runtime.h>
#include <math.h>

#define Bn   32
#define Tn   512
#define Mn   2048
#define Ln   1024
#define NMEL 80
#define DSPK 256

#define MEL_BLOCKS  1024
#define ATTN_CHUNKS 32                   // 16 t-rows per chunk
#define ATTN_BLOCKS (Bn * ATTN_CHUNKS)   // 1024
#define DUR_BLOCKS  64
#define GRID_TOTAL  (MEL_BLOCKS + ATTN_BLOCKS + DUR_BLOCKS)  // 2112
#define NTHREADS    256

// ---- scratch (per-block slots -> deterministic sums) ----
__device__ float g_mel_partial[MEL_BLOCKS];
__device__ float g_post_partial[MEL_BLOCKS];
__device__ float g_attn_num[ATTN_BLOCKS];
__device__ float g_attn_den[ATTN_BLOCKS];
__device__ float g_dur_partial[DUR_BLOCKS];
__device__ unsigned int g_counter = 0;   // self-resetting each launch

__device__ __forceinline__ float block_reduce(float v, float* sh) {
    int tid = threadIdx.x;
    #pragma unroll
    for (int o = 16; o > 0; o >>= 1) v += __shfl_down_sync(0xffffffffu, v, o);
    if ((tid & 31) == 0) sh[tid >> 5] = v;
    __syncthreads();
    float r = 0.0f;
    if (tid < 8) {
        r = sh[tid];
        #pragma unroll
        for (int o = 4; o > 0; o >>= 1) r += __shfl_down_sync(0xffu, r, o);
    }
    __syncthreads();
    return r;          // valid on tid 0
}

__global__ __launch_bounds__(NTHREADS)
void fused_loss_kernel(const float* __restrict__ mel_t,
                       const float* __restrict__ mel_p,
                       const float* __restrict__ post_p,
                       const int*   __restrict__ mel_lens,
                       const float* __restrict__ attn,
                       const int*   __restrict__ x_len,
                       const int*   __restrict__ lip_len,
                       const float* __restrict__ logdur_p,
                       const int*   __restrict__ dur_t,
                       const float* __restrict__ spk_p,
                       const float* __restrict__ spk_e,
                       float* __restrict__ out)
{
    __shared__ float sh[8];
    const int bid = blockIdx.x;
    const int tid = threadIdx.x;

    if (bid < MEL_BLOCKS) {
        // ---- masked |pred-tgt| sums over [B, M, 80] (float4 grid-stride) ----
        __shared__ int s_len[Bn];
        if (tid < Bn) s_len[tid] = mel_lens[tid];
        __syncthreads();
        const int F = Bn * Mn * (NMEL / 4);
        float s1 = 0.0f, s2 = 0.0f;
        for (int f = bid * NTHREADS + tid; f < F; f += MEL_BLOCKS * NTHREADS) {
            int b = f / (Mn * (NMEL / 4));
            int m = (f / (NMEL / 4)) % Mn;
            if (m < s_len[b]) {          // masked rows: no load, no traffic
                float4 t4 = reinterpret_cast<const float4*>(mel_t)[f];
                float4 p4 = reinterpret_cast<const float4*>(mel_p)[f];
                float4 q4 = reinterpret_cast<const float4*>(post_p)[f];
                s1 += fabsf(p4.x - t4.x) + fabsf(p4.y - t4.y)
                    + fabsf(p4.z - t4.z) + fabsf(p4.w - t4.w);
                s2 += fabsf(q4.x - t4.x) + fabsf(q4.y - t4.y)
                    + fabsf(q4.z - t4.z) + fabsf(q4.w - t4.w);
            }
        }
        float r1 = block_reduce(s1, sh);
        float r2 = block_reduce(s2, sh);
        if (tid == 0) { g_mel_partial[bid] = r1; g_post_partial[bid] = r2; }
    } else if (bid < MEL_BLOCKS + ATTN_BLOCKS) {
        // ---- attention diagonal-focus partials ----
        const int id = bid - MEL_BLOCKS;
        const int b  = id / ATTN_CHUNKS;
        const int c  = id % ATTN_CHUNKS;
        const int xl = x_len[b];
        const int ll = lip_len[b];
        const float ks = (float)ll / (float)xl;
        const float da = (float)ll * 0.125f;       // / DIAR(8)
        float num = 0.0f, den = 0.0f;
        const int l0 = tid * 4;
        const bool lane_live = (l0 < ll);          // skip masked tail -> no load
        const int t_beg = c * (Tn / ATTN_CHUNKS);
        const int t_end = t_beg + (Tn / ATTN_CHUNKS);
        for (int t = t_beg; t < t_end; ++t) {
            if (t >= xl) break;                    // rows monotonically masked
            if (!lane_live) continue;
            const float kt = __fmul_rn(ks, (float)t);
            const float y1 = floorf(__fadd_rn(kt, da));
            const float y2 = floorf(fmaxf(__fsub_rn(kt, da), 0.0f));
            float4 v = reinterpret_cast<const float4*>(
                           attn + ((size_t)b * Tn + t) * Ln)[tid];
            #pragma unroll
            for (int j = 0; j < 4; ++j) {
                const float vv = (&v.x)[j];
                const int   l  = l0 + j;
                if (l < ll) {
                    den += vv;
                    const float lf = (float)l;
                    if (lf >= y2 && lf < y1) num += vv;
                }
            }
        }
        float rn = block_reduce(num, sh);
        float rd = block_reduce(den, sh);
        if (tid == 0) { g_attn_num[id] = rn; g_attn_den[id] = rd; }
    } else {
        // ---- duration MSE in log domain ----
        const int id  = bid - MEL_BLOCKS - ATTN_BLOCKS;   // 0..63
        const int idx = id * NTHREADS + tid;              // < B*T
        const int b = idx / Tn;
        const int t = idx % Tn;
        float s = 0.0f;
        if (t < x_len[b]) {
            float d = logdur_p[idx] - logf((float)dur_t[idx] + 1.0f);
            s = d * d;
        }
        float r = block_reduce(s, sh);
        if (tid == 0) g_dur_partial[id] = r;
    }

    // ================= last-block finalization =================
    __shared__ bool s_last;
    __threadfence();
    if (tid == 0) {
        unsigned int old = atomicAdd(&g_counter, 1u);
        s_last = (old == GRID_TOTAL - 1);
    }
    __syncthreads();
    if (!s_last) return;

    __shared__ float res[4];   // 0:mel 1:post 2:dur 3:focus_sum

    // mel / postnet totals
    float s1 = 0.0f, s2 = 0.0f;
    for (int i = tid; i < MEL_BLOCKS; i += NTHREADS) {
        s1 += g_mel_partial[i];
        s2 += g_post_partial[i];
    }
    float r = block_reduce(s1, sh); if (tid == 0) res[0] = r;
    r = block_reduce(s2, sh);       if (tid == 0) res[1] = r;

    // duration total
    float sd = 0.0f;
    for (int i = tid; i < DUR_BLOCKS; i += NTHREADS) sd += g_dur_partial[i];
    r = block_reduce(sd, sh);       if (tid == 0) res[2] = r;

    // per-batch focus -> mean (warp 0, lane = batch)
    if (tid < 32) {
        float n = 0.0f, d = 0.0f;
        #pragma unroll 8
        for (int c = 0; c < ATTN_CHUNKS; ++c) {
            n += g_attn_num[tid * ATTN_CHUNKS + c];
            d += g_attn_den[tid * ATTN_CHUNKS + c];
        }
        float focus = n / d;
        #pragma unroll
        for (int o = 16; o > 0; o >>= 1) focus += __shfl_down_sync(0xffffffffu, focus, o);
        if (tid == 0) res[3] = focus;
    }

    // speaker cosine: 8 warps x 4 batches
    {
        const int w = tid >> 5, lane = tid & 31;
        float acc = 0.0f;
        for (int i = 0; i < 4; ++i) {
            const int b = w * 4 + i;
            float dot = 0.0f, n1 = 0.0f, n2 = 0.0f;
            #pragma unroll
            for (int e = 0; e < DSPK / 32; ++e) {
                float p = spk_p[b * DSPK + lane + e * 32];
                float q = spk_e[b * DSPK + lane + e * 32];
                dot += p * q; n1 += p * p; n2 += q * q;
            }
            #pragma unroll
            for (int o = 16; o > 0; o >>= 1) {
                dot += __shfl_down_sync(0xffffffffu, dot, o);
                n1  += __shfl_down_sync(0xffffffffu, n1, o);
                n2  += __shfl_down_sync(0xffffffffu, n2, o);
            }
            if (lane == 0) {
                const float eps = 1e-6f;
                float cosv = dot / (fmaxf(sqrtf(n1), eps) * fmaxf(sqrtf(n2), eps));
                acc += 1.0f - cosv;
            }
        }
        __syncthreads();           // sh[] free again
        if (lane == 0) sh[w] = acc;
    }
    __syncthreads();

    if (tid == 0) {
        float spk_sum = 0.0f;
        #pragma unroll
        for (int w = 0; w < 8; ++w) spk_sum += sh[w];

        float cnt_rows = 0.0f, xsum = 0.0f;
        for (int b = 0; b < Bn; ++b) {
            cnt_rows += (float)mel_lens[b];
            xsum     += (float)x_len[b];
        }
        const float cnt = cnt_rows * (float)NMEL;

        const float mel_loss      = res[0] / cnt;
        const float postnet_loss  = res[1] / cnt;
        const float duration_loss = res[2] / xsum;
        const float speaker_loss  = spk_sum / (float)Bn;
        const float diagonal_loss = 0.1f * -logf(res[3] / (float)Bn);
        const float total = mel_loss + postnet_loss + duration_loss
                          + speaker_loss + diagonal_loss;
        out[0] = total;
        out[1] = mel_loss;
        out[2] = postnet_loss;
        out[3] = speaker_loss;
        out[4] = duration_loss;
        out[5] = diagonal_loss;

        g_counter = 0;            // reset for next graph replay
    }
}

extern "C" void kernel_launch(void* const* d_in, const int* in_sizes, int n_in,
                              void* d_out, int out_size)
{
    const float* mel_t    = (const float*)d_in[2];
    const int*   mel_lens = (const int*)  d_in[5];
    const int*   dur_t    = (const int*)  d_in[6];
    const float* mel_p    = (const float*)d_in[8];
    const float* post_p   = (const float*)d_in[9];
    const float* logdur_p = (const float*)d_in[10];
    const float* spk_p    = (const float*)d_in[14];
    const float* spk_e    = (const float*)d_in[15];
    const float* attn     = (const float*)d_in[16];
    const int*   x_len    = (const int*)  d_in[17];
    const int*   lip_len  = (const int*)  d_in[18];

    fused_loss_kernel<<<GRID_TOTAL, NTHREADS>>>(
        mel_t, mel_p, post_p, mel_lens, attn, x_len, lip_len,
        logdur_p, dur_t, spk_p, spk_e, (float*)d_out);
}

// round 3
// speedup vs baseline: 1.4009x; 1.4009x over previous
#include <cuda_runtime.h>
#include <math.h>

#define Bn   32
#define Tn   512
#define Mn   2048
#define Ln   1024
#define NMEL 80
#define DSPK 256

#define MEL_BLOCKS  512                  // 16 per batch, 128 mel-rows each
#define ATTN_BLOCKS 512                  // 16 per batch, 32 t-rows each
#define DUR_BLOCKS  64
#define GRID1       (MEL_BLOCKS + ATTN_BLOCKS + DUR_BLOCKS)
#define NTHREADS    256

// ---- per-block partial slots (deterministic fixed-order combine) ----
__device__ float g_mel_partial[MEL_BLOCKS];
__device__ float g_post_partial[MEL_BLOCKS];
__device__ float g_attn_num[ATTN_BLOCKS];   // layout: b*16 + chunk
__device__ float g_attn_den[ATTN_BLOCKS];
__device__ float g_dur_partial[DUR_BLOCKS];

__device__ __forceinline__ float block_reduce256(float v, float* sh) {
    int tid = threadIdx.x;
    #pragma unroll
    for (int o = 16; o > 0; o >>= 1) v += __shfl_down_sync(0xffffffffu, v, o);
    if ((tid & 31) == 0) sh[tid >> 5] = v;
    __syncthreads();
    float r = 0.0f;
    if (tid < 8) {
        r = sh[tid];
        #pragma unroll
        for (int o = 4; o > 0; o >>= 1) r += __shfl_down_sync(0xffu, r, o);
    }
    __syncthreads();
    return r;   // valid on tid 0
}

__global__ __launch_bounds__(NTHREADS)
void partials_kernel(const float* __restrict__ mel_t,
                     const float* __restrict__ mel_p,
                     const float* __restrict__ post_p,
                     const int*   __restrict__ mel_lens,
                     const float* __restrict__ attn,
                     const int*   __restrict__ x_len,
                     const int*   __restrict__ lip_len,
                     const float* __restrict__ logdur_p,
                     const int*   __restrict__ dur_t)
{
    __shared__ float sh[8];
    const int bid = blockIdx.x;
    const int tid = threadIdx.x;

    if (bid < MEL_BLOCKS) {
        // ---- tile: batch b, mel-rows [m0, m0+128), 2560 float4s / array ----
        const int b   = bid >> 4;
        const int m0  = (bid & 15) << 7;
        const int len = mel_lens[b];
        float s1 = 0.0f, s2 = 0.0f;

        const size_t base = ((size_t)b * Mn + m0) * (NMEL / 4);
        const float4* __restrict__ t4 = reinterpret_cast<const float4*>(mel_t)  + base;
        const float4* __restrict__ p4 = reinterpret_cast<const float4*>(mel_p)  + base;
        const float4* __restrict__ q4 = reinterpret_cast<const float4*>(post_p) + base;

        if (m0 + 128 <= len) {
            // fast path: whole tile valid, branch-free, loads batched per pair
            #pragma unroll
            for (int u = 0; u < 10; u += 2) {
                const int i0 = u * NTHREADS + tid;
                const int i1 = i0 + NTHREADS;
                float4 ta = t4[i0], pa = p4[i0], qa = q4[i0];
                float4 tb = t4[i1], pb = p4[i1], qb = q4[i1];
                s1 += fabsf(pa.x - ta.x) + fabsf(pa.y - ta.y)
                    + fabsf(pa.z - ta.z) + fabsf(pa.w - ta.w);
                s2 += fabsf(qa.x - ta.x) + fabsf(qa.y - ta.y)
                    + fabsf(qa.z - ta.z) + fabsf(qa.w - ta.w);
                s1 += fabsf(pb.x - tb.x) + fabsf(pb.y - tb.y)
                    + fabsf(pb.z - tb.z) + fabsf(pb.w - tb.w);
                s2 += fabsf(qb.x - tb.x) + fabsf(qb.y - tb.y)
                    + fabsf(qb.z - tb.z) + fabsf(qb.w - tb.w);
            }
        } else if (m0 < len) {
            // straddle tile: valid prefix only
            const int nv = (len - m0) * (NMEL / 4);
            for (int i = tid; i < nv; i += NTHREADS) {
                float4 ta = t4[i], pa = p4[i], qa = q4[i];
                s1 += fabsf(pa.x - ta.x) + fabsf(pa.y - ta.y)
                    + fabsf(pa.z - ta.z) + fabsf(pa.w - ta.w);
                s2 += fabsf(qa.x - ta.x) + fabsf(qa.y - ta.y)
                    + fabsf(qa.z - ta.z) + fabsf(qa.w - ta.w);
            }
        }
        float r1 = block_reduce256(s1, sh);
        float r2 = block_reduce256(s2, sh);
        if (tid == 0) { g_mel_partial[bid] = r1; g_post_partial[bid] = r2; }
    } else if (bid < MEL_BLOCKS + ATTN_BLOCKS) {
        // ---- attn tile: batch b, t-rows [t0, t0+32), lane owns column l0..l0+3
        const int id = bid - MEL_BLOCKS;
        const int b  = id >> 4;
        const int t0 = (id & 15) << 5;
        const int xl = x_len[b];
        const int ll = lip_len[b];
        const float ks = (float)ll / (float)xl;
        const float da = (float)ll * 0.125f;        // lip_len / DIAR(8)

        __shared__ float s_y1[32], s_y2[32];
        if (tid < 32) {
            const float kt = __fmul_rn(ks, (float)(t0 + tid));
            s_y1[tid] = floorf(__fadd_rn(kt, da));
            s_y2[tid] = floorf(fmaxf(__fsub_rn(kt, da), 0.0f));
        }
        __syncthreads();

        float num = 0.0f, den = 0.0f;
        const int l0 = tid << 2;
        const int nt = min(t0 + 32, xl) - t0;       // rows monotonically masked
        if (l0 < ll && nt > 0) {
            const float lf0 = (float)l0, lf1 = lf0 + 1.0f,
                        lf2 = lf0 + 2.0f, lf3 = lf0 + 3.0f;
            const bool v1 = (l0 + 1 < ll), v2 = (l0 + 2 < ll), v3 = (l0 + 3 < ll);
            const float4* __restrict__ a4 =
                reinterpret_cast<const float4*>(attn) +
                ((size_t)b * Tn + t0) * (Ln / 4) + tid;
            #pragma unroll 2
            for (int t = 0; t < nt; ++t) {
                float4 v = a4[(size_t)t * (Ln / 4)];
                const float y1 = s_y1[t], y2 = s_y2[t];
                den += v.x;
                if (lf0 >= y2 && lf0 < y1) num += v.x;
                if (v1) { den += v.y; if (lf1 >= y2 && lf1 < y1) num += v.y; }
                if (v2) { den += v.z; if (lf2 >= y2 && lf2 < y1) num += v.z; }
                if (v3) { den += v.w; if (lf3 >= y2 && lf3 < y1) num += v.w; }
            }
        }
        float rn = block_reduce256(num, sh);
        float rd = block_reduce256(den, sh);
        if (tid == 0) { g_attn_num[id] = rn; g_attn_den[id] = rd; }
    } else {
        // ---- duration MSE in log domain ----
        const int id  = bid - MEL_BLOCKS - ATTN_BLOCKS;  // 0..63
        const int idx = id * NTHREADS + tid;             // < B*T
        const int b = idx / Tn;
        const int t = idx % Tn;
        float s = 0.0f;
        if (t < x_len[b]) {
            float d = logdur_p[idx] - logf((float)dur_t[idx] + 1.0f);
            s = d * d;
        }
        float r = block_reduce256(s, sh);
        if (tid == 0) g_dur_partial[id] = r;
    }
}

__device__ __forceinline__ float block_reduce1024(float v, float* sh) {
    int tid = threadIdx.x;
    #pragma unroll
    for (int o = 16; o > 0; o >>= 1) v += __shfl_down_sync(0xffffffffu, v, o);
    if ((tid & 31) == 0) sh[tid >> 5] = v;
    __syncthreads();
    float r = 0.0f;
    if (tid < 32) {
        r = sh[tid];
        #pragma unroll
        for (int o = 16; o > 0; o >>= 1) r += __shfl_down_sync(0xffffffffu, r, o);
    }
    __syncthreads();
    return r;   // valid on tid 0
}

__global__ __launch_bounds__(1024)
void finalize_kernel(const float* __restrict__ spk_p,
                     const float* __restrict__ spk_e,
                     const int*   __restrict__ mel_lens,
                     const int*   __restrict__ x_len,
                     float* __restrict__ out)
{
    __shared__ float sh[32];
    __shared__ float resv[8];   // 0 mel,1 post,2 dur,3 focus,4 spk,5 cnt,6 xsum
    const int tid  = threadIdx.x;
    const int warp = tid >> 5, lane = tid & 31;

    // ---- issue ALL global reads up-front (overlap latencies) ----
    const float vm = (tid < MEL_BLOCKS)  ? g_mel_partial[tid]  : 0.0f;
    const float vp = (tid < MEL_BLOCKS)  ? g_post_partial[tid] : 0.0f;
    const float vd = (tid < DUR_BLOCKS)  ? g_dur_partial[tid]  : 0.0f;
    float an = 0.0f, ad = 0.0f;
    if (tid < ATTN_BLOCKS) { an = g_attn_num[tid]; ad = g_attn_den[tid]; }
    const float cr = (tid < Bn) ? (float)mel_lens[tid] : 0.0f;
    const float xr = (tid < Bn) ? (float)x_len[tid]    : 0.0f;
    // speaker: warp w handles batch w (32 warps == 32 batches)
    float dot = 0.0f, n1 = 0.0f, n2 = 0.0f;
    #pragma unroll
    for (int e = 0; e < DSPK / 32; ++e) {
        const float p = spk_p[warp * DSPK + lane + e * 32];
        const float q = spk_e[warp * DSPK + lane + e * 32];
        dot += p * q; n1 += p * p; n2 += q * q;
    }

    // ---- speaker warp reduce ----
    #pragma unroll
    for (int o = 16; o > 0; o >>= 1) {
        dot += __shfl_down_sync(0xffffffffu, dot, o);
        n1  += __shfl_down_sync(0xffffffffu, n1, o);
        n2  += __shfl_down_sync(0xffffffffu, n2, o);
    }
    float spk_term = 0.0f;
    if (lane == 0) {
        const float eps = 1e-6f;
        spk_term = 1.0f - dot / (fmaxf(sqrtf(n1), eps) * fmaxf(sqrtf(n2), eps));
    }

    // ---- attn focus: segmented width-16 reduce (16 chunks per batch) ----
    #pragma unroll
    for (int o = 8; o > 0; o >>= 1) {
        an += __shfl_down_sync(0xffffffffu, an, o, 16);
        ad += __shfl_down_sync(0xffffffffu, ad, o, 16);
    }
    float focus = 0.0f;
    if (tid < ATTN_BLOCKS && (tid & 15) == 0) focus = an / ad;

    // ---- block-wide combines (fixed order -> deterministic) ----
    float r;
    r = block_reduce1024(vm, sh);       if (tid == 0) resv[0] = r;
    r = block_reduce1024(vp, sh);       if (tid == 0) resv[1] = r;
    r = block_reduce1024(vd, sh);       if (tid == 0) resv[2] = r;
    r = block_reduce1024(focus, sh);    if (tid == 0) resv[3] = r;
    r = block_reduce1024(spk_term, sh); if (tid == 0) resv[4] = r;
    r = block_reduce1024(cr, sh);       if (tid == 0) resv[5] = r;
    r = block_reduce1024(xr, sh);       if (tid == 0) resv[6] = r;
    __syncthreads();

    if (tid == 0) {
        const float cnt = resv[5] * (float)NMEL;
        const float mel_loss      = resv[0] / cnt;               // MEL_LW = 1
        const float postnet_loss  = resv[1] / cnt;
        const float duration_loss = resv[2] / resv[6];           // DUR_W = 1
        const float speaker_loss  = resv[4] / (float)Bn;         // SPK_W = 1
        const float diagonal_loss = 0.1f * -logf(resv[3] / (float)Bn);
        const float total = mel_loss + postnet_loss + duration_loss
                          + speaker_loss + diagonal_loss;
        out[0] = total;
        out[1] = mel_loss;
        out[2] = postnet_loss;
        out[3] = speaker_loss;
        out[4] = duration_loss;
        out[5] = diagonal_loss;
    }
}

extern "C" void kernel_launch(void* const* d_in, const int* in_sizes, int n_in,
                              void* d_out, int out_size)
{
    const float* mel_t    = (const float*)d_in[2];
    const int*   mel_lens = (const int*)  d_in[5];
    const int*   dur_t    = (const int*)  d_in[6];
    const float* mel_p    = (const float*)d_in[8];
    const float* post_p   = (const float*)d_in[9];
    const float* logdur_p = (const float*)d_in[10];
    const float* spk_p    = (const float*)d_in[14];
    const float* spk_e    = (const float*)d_in[15];
    const float* attn     = (const float*)d_in[16];
    const int*   x_len    = (const int*)  d_in[17];
    const int*   lip_len  = (const int*)  d_in[18];

    partials_kernel<<<GRID1, NTHREADS>>>(
        mel_t, mel_p, post_p, mel_lens, attn, x_len, lip_len, logdur_p, dur_t);
    finalize_kernel<<<1, 1024>>>(spk_p, spk_e, mel_lens, x_len, (float*)d_out);
}